// round 15
// baseline (speedup 1.0000x reference)
#include <cuda_runtime.h>
#include <cuda_fp16.h>
#include <math.h>
#include <stdint.h>

// ---------------------------------------------------------------------------
// EfficientSelfAttention (PVT SRA): B=4, N=4096 (64x64), C=512, heads=8,
// head_dim=64, SR=2 -> N_kv=1024.  fp16 m16n8k16 mma.sync (fp32 accum).
// Round 15: R14 + (a) KV V-epilogue smem transpose -> coalesced 16B stores,
// (b) conv split-K=2 -> ln reads 2 partials.
// ---------------------------------------------------------------------------

__device__ __half  g_xt[8388608];   // x as half [16384][512]
__device__ float   g_xr[2097152];   // conv partial z=0 (fp32, +bias)
__device__ float   g_xr2[2097152];  // conv partial z=1
__device__ __half  g_xrh[2097152];  // LN output half
__device__ __half  g_k[2097152];    // [bh][m][d]
__device__ __half  g_v[2097152];    // TRANSPOSED: [bh][d][m]
__device__ __half  g_att[8388608];  // [b,n, h*64+d]
__device__ uint32_t g_q[4194304];   // Q in fp16 A-fragment order (log2-scaled)
__device__ __half  g_wq[262144];    // W^T [N][K]
__device__ __half  g_wkv[524288];
__device__ __half  g_wp[262144];
__device__ __half  g_wsr[1048576];

#define QSCALE 0.18033688011112042f   // 0.125 * log2(e)

__device__ __forceinline__ uint32_t pack2(float a, float b) {
    __half2 h = __floats2half2_rn(a, b);
    return *(uint32_t*)&h;
}
__device__ __forceinline__ uint32_t h2ex2(uint32_t x) {
    uint32_t r;
    asm("ex2.approx.f16x2 %0, %1;" : "=r"(r) : "r"(x));
    return r;
}

__device__ __forceinline__ void mma16(float* c, const uint32_t* a, const uint32_t* b) {
    asm("mma.sync.aligned.m16n8k16.row.col.f32.f16.f16.f32 "
        "{%0,%1,%2,%3}, {%4,%5,%6,%7}, {%8,%9}, {%0,%1,%2,%3};"
        : "+f"(c[0]), "+f"(c[1]), "+f"(c[2]), "+f"(c[3])
        : "r"(a[0]), "r"(a[1]), "r"(a[2]), "r"(a[3]), "r"(b[0]), "r"(b[1]));
}

__device__ __forceinline__ void cp16(uint32_t dst, const void* src) {
    asm volatile("cp.async.cg.shared.global [%0], [%1], 16;" :: "r"(dst), "l"(src));
}
__device__ __forceinline__ void cp_commit() {
    asm volatile("cp.async.commit_group;");
}
template <int N>
__device__ __forceinline__ void cp_wait() {
    asm volatile("cp.async.wait_group %0;" :: "n"(N));
}

// ---------------------------------------------------------------------------
// Merged pre-pass: blocks [0,8192) convert x -> half; [8192,10240) transpose
// weights fp32 [K][N] -> half [N][K].
// ---------------------------------------------------------------------------
__global__ void __launch_bounds__(256) prepass(
    const float4* __restrict__ x,
    const float* __restrict__ wq, const float* __restrict__ wkv,
    const float* __restrict__ wp, const float* __restrict__ wsr)
{
    __shared__ float tile[32][33];
    if (blockIdx.x < 8192) {
        int i = blockIdx.x * 256 + threadIdx.x;
        float4 v = x[i];
        uint2 o;
        o.x = pack2(v.x, v.y);
        o.y = pack2(v.z, v.w);
        *(uint2*)(g_xt + (size_t)i * 4) = o;
        return;
    }
    int t = blockIdx.x - 8192;
    const float* src; __half* dst; int K, N, tk, tn;
    if (t < 256)       { src = wq;  dst = g_wq;  K = 512;  N = 512;  tk = t >> 4; tn = t & 15; }
    else if (t < 768)  { t -= 256;  src = wkv; dst = g_wkv; K = 512;  N = 1024; tk = t >> 5; tn = t & 31; }
    else if (t < 1024) { t -= 768;  src = wp;  dst = g_wp;  K = 512;  N = 512;  tk = t >> 4; tn = t & 15; }
    else               { t -= 1024; src = wsr; dst = g_wsr; K = 2048; N = 512;  tk = t >> 4; tn = t & 15; }

    int tx = threadIdx.x & 31, ty = threadIdx.x >> 5;
    int k0 = tk * 32, n0 = tn * 32;
    #pragma unroll
    for (int i = 0; i < 4; i++)
        tile[tx][ty + 8 * i] = src[(size_t)(k0 + ty + 8 * i) * N + n0 + tx];
    __syncthreads();
    #pragma unroll
    for (int i = 0; i < 4; i++) {
        int row = ty + 8 * i;
        dst[(size_t)(n0 + row) * K + k0 + tx] = __float2half_rn(tile[row][tx]);
    }
}

// ---------------------------------------------------------------------------
// WIDE fp16 GEMM: block 128x256, BK=32, 3-stage cp.async ring, 8 warps (2x4),
// warp tile 64x64.
// MODE 0: A=g_xt,  B=g_wq^T -> g_q fragment-order (*QSCALE, +bias, half)
// MODE 3: A=g_att, B=g_wp^T -> Cout fp32 (+bias)
// ---------------------------------------------------------------------------
template <int MODE>
__global__ void __launch_bounds__(256) gemm_wide(
    const float* __restrict__ bias, float* __restrict__ Cout, int K)
{
    extern __shared__ uint32_t smem[];
    const int OB = 3 * 128 * 20;  // 7680

    const int tid = threadIdx.x, lane = tid & 31, warp = tid >> 5;
    const int wm = warp >> 2, wn = warp & 3;
    const int l2 = lane >> 2, l4 = lane & 3;
    const int m0 = blockIdx.y * 128, n0 = blockIdx.x * 256;

    const __half* Ap = (MODE == 3) ? g_att : g_xt;
    const __half* Bp = (MODE == 3) ? g_wp : g_wq;

    const uint32_t sbase = (uint32_t)__cvta_generic_to_shared(smem);

    float acc[4][8][4] = {};

    auto load_tiles = [&](int s, int k0) {
        #pragma unroll
        for (int u = 0; u < 2; u++) {
            int e = u * 256 + tid;
            int row = e >> 2, cw = e & 3;
            cp16(sbase + (uint32_t)(s * 2560 + row * 20 + cw * 4) * 4,
                 Ap + (size_t)(m0 + row) * K + k0 + cw * 8);
        }
        #pragma unroll
        for (int u = 0; u < 4; u++) {
            int e = u * 256 + tid;
            int row = e >> 2, cw = e & 3;
            cp16(sbase + (uint32_t)(OB + s * 5120 + row * 20 + cw * 4) * 4,
                 Bp + (size_t)(n0 + row) * K + k0 + cw * 8);
        }
    };

    const int KT = K >> 5;
    load_tiles(0, 0);
    cp_commit();
    load_tiles(1, 32);
    cp_commit();

    for (int kt = 0; kt < KT; kt++) {
        if (kt < KT - 1) { cp_wait<1>(); } else { cp_wait<0>(); }
        __syncthreads();
        if (kt + 2 < KT) {
            load_tiles((kt + 2) % 3, (kt + 2) * 32);
            cp_commit();
        }
        const int stage = kt % 3;

        const uint32_t* Ab = smem + stage * 2560;
        const uint32_t* Bb = smem + OB + stage * 5120;
        #pragma unroll
        for (int j = 0; j < 2; j++) {
            uint32_t a[4][4], bf[8][2];
            #pragma unroll
            for (int mt = 0; mt < 4; mt++) {
                int r = wm * 64 + mt * 16 + l2;
                a[mt][0] = Ab[r * 20 + j * 8 + l4];
                a[mt][1] = Ab[(r + 8) * 20 + j * 8 + l4];
                a[mt][2] = Ab[r * 20 + j * 8 + l4 + 4];
                a[mt][3] = Ab[(r + 8) * 20 + j * 8 + l4 + 4];
            }
            #pragma unroll
            for (int nt = 0; nt < 8; nt++) {
                int col = wn * 64 + nt * 8 + l2;
                bf[nt][0] = Bb[col * 20 + j * 8 + l4];
                bf[nt][1] = Bb[col * 20 + j * 8 + l4 + 4];
            }
            #pragma unroll
            for (int mt = 0; mt < 4; mt++)
                #pragma unroll
                for (int nt = 0; nt < 8; nt++)
                    mma16(acc[mt][nt], a[mt], bf[nt]);
        }
        __syncthreads();
    }

    #pragma unroll
    for (int mt = 0; mt < 4; mt++) {
        #pragma unroll
        for (int nt = 0; nt < 8; nt++) {
            int r = m0 + wm * 64 + mt * 16 + l2;
            int c = n0 + wn * 64 + nt * 8 + l4 * 2;
            float b0 = bias[c], b1 = bias[c + 1];
            float v00 = acc[mt][nt][0] + b0, v01 = acc[mt][nt][1] + b1;
            float v10 = acc[mt][nt][2] + b0, v11 = acc[mt][nt][3] + b1;
            if (MODE == 0) {
                int b_ = r >> 12, nq = r & 4095;
                int h = c >> 6, d = c & 63;
                int bh = b_ * 8 + h, ntile = nq >> 4;
                int j = d >> 4, wsel = (d >> 3) & 1;
                size_t base = (((size_t)(bh * 256 + ntile) * 4 + j) * 32 + lane) * 4 + wsel * 2;
                g_q[base]     = pack2(v00 * QSCALE, v01 * QSCALE);
                g_q[base + 1] = pack2(v10 * QSCALE, v11 * QSCALE);
            } else {
                *(float2*)(Cout + (size_t)r * 512 + c) = make_float2(v00, v01);
                *(float2*)(Cout + (size_t)(r + 8) * 512 + c) = make_float2(v10, v11);
            }
        }
    }
}

// ---------------------------------------------------------------------------
// Narrow fp16 GEMM: block 128x128, BK=32, 3-stage ring, warp tile 32x64.
// MODE 1: A=g_xt (conv patch gather), B=g_wsr^T -> split-K z=0/1 partials
// MODE 2: A=g_xrh, B=g_wkv^T -> g_k (+bias) / g_v (smem-transposed, +bias)
// ---------------------------------------------------------------------------
template <int MODE>
__global__ void __launch_bounds__(256) gemm_h(
    const float* __restrict__ bias, int Kfull)
{
    extern __shared__ uint32_t smem[];
    const int OB = 3 * 128 * 20;

    const int tid = threadIdx.x, lane = tid & 31, warp = tid >> 5;
    const int wm = warp >> 1, wn = warp & 1;
    const int l2 = lane >> 2, l4 = lane & 3;
    const int m0 = blockIdx.y * 128, n0 = blockIdx.x * 128;
    const int kz0 = (MODE == 1) ? (int)blockIdx.z * 1024 : 0;
    const int Kblk = (MODE == 1) ? 1024 : Kfull;

    const __half* Ap = (MODE == 2) ? g_xrh : g_xt;
    const __half* Bp = (MODE == 1) ? g_wsr : g_wkv;

    const uint32_t sbase = (uint32_t)__cvta_generic_to_shared(smem);

    float acc[2][8][4] = {};

    auto load_tiles = [&](int s, int kg) {
        #pragma unroll
        for (int u = 0; u < 2; u++) {
            int e = u * 256 + tid;
            int row = e >> 2, cw = e & 3;
            const __half* src;
            if (MODE == 1) {
                int m = m0 + row;
                int b = m >> 10, rem = m & 1023;
                int oh = rem >> 5, ow = rem & 31;
                int k = kg + cw * 8;
                int di = k >> 10, dj = (k >> 9) & 1, c = k & 511;
                int grow = (b << 12) + (((oh << 1) + di) << 6) + (ow << 1) + dj;
                src = Ap + (size_t)grow * 512 + c;
            } else {
                src = Ap + (size_t)(m0 + row) * Kfull + kg + cw * 8;
            }
            cp16(sbase + (uint32_t)(s * 2560 + row * 20 + cw * 4) * 4, src);
        }
        #pragma unroll
        for (int u = 0; u < 2; u++) {
            int e = u * 256 + tid;
            int row = e >> 2, cw = e & 3;
            cp16(sbase + (uint32_t)(OB + s * 2560 + row * 20 + cw * 4) * 4,
                 Bp + (size_t)(n0 + row) * Kfull + kg + cw * 8);
        }
    };

    const int KT = Kblk >> 5;
    load_tiles(0, kz0);
    cp_commit();
    load_tiles(1, kz0 + 32);
    cp_commit();

    for (int kt = 0; kt < KT; kt++) {
        if (kt < KT - 1) { cp_wait<1>(); } else { cp_wait<0>(); }
        __syncthreads();
        if (kt + 2 < KT) {
            load_tiles((kt + 2) % 3, kz0 + (kt + 2) * 32);
            cp_commit();
        }
        const int stage = kt % 3;

        const uint32_t* Ab = smem + stage * 2560;
        const uint32_t* Bb = smem + OB + stage * 2560;
        #pragma unroll
        for (int j = 0; j < 2; j++) {
            uint32_t a[2][4], bf[8][2];
            #pragma unroll
            for (int mt = 0; mt < 2; mt++) {
                int r = wm * 32 + mt * 16 + l2;
                a[mt][0] = Ab[r * 20 + j * 8 + l4];
                a[mt][1] = Ab[(r + 8) * 20 + j * 8 + l4];
                a[mt][2] = Ab[r * 20 + j * 8 + l4 + 4];
                a[mt][3] = Ab[(r + 8) * 20 + j * 8 + l4 + 4];
            }
            #pragma unroll
            for (int nt = 0; nt < 8; nt++) {
                int col = wn * 64 + nt * 8 + l2;
                bf[nt][0] = Bb[col * 20 + j * 8 + l4];
                bf[nt][1] = Bb[col * 20 + j * 8 + l4 + 4];
            }
            #pragma unroll
            for (int mt = 0; mt < 2; mt++)
                #pragma unroll
                for (int nt = 0; nt < 8; nt++)
                    mma16(acc[mt][nt], a[mt], bf[nt]);
        }
        __syncthreads();
    }

    if (MODE == 1) {
        #pragma unroll
        for (int mt = 0; mt < 2; mt++) {
            #pragma unroll
            for (int nt = 0; nt < 8; nt++) {
                int r = m0 + wm * 32 + mt * 16 + l2;
                int c = n0 + wn * 64 + nt * 8 + l4 * 2;
                float b0 = 0.0f, b1 = 0.0f;
                if (blockIdx.z == 0) { b0 = bias[c]; b1 = bias[c + 1]; }
                float* dst = (blockIdx.z == 0) ? g_xr : g_xr2;
                *(float2*)(dst + (size_t)r * 512 + c) =
                    make_float2(acc[mt][nt][0] + b0, acc[mt][nt][1] + b1);
                *(float2*)(dst + (size_t)(r + 8) * 512 + c) =
                    make_float2(acc[mt][nt][2] + b0, acc[mt][nt][3] + b1);
            }
        }
        return;
    }

    // MODE 2 epilogue
    if (n0 < 512) {
        // K half: coalesced 32-bit pack2 stores, as before
        #pragma unroll
        for (int mt = 0; mt < 2; mt++) {
            #pragma unroll
            for (int nt = 0; nt < 8; nt++) {
                int r = m0 + wm * 32 + mt * 16 + l2;
                int c = n0 + wn * 64 + nt * 8 + l4 * 2;
                float b0 = bias[c], b1 = bias[c + 1];
                float v00 = acc[mt][nt][0] + b0, v01 = acc[mt][nt][1] + b1;
                float v10 = acc[mt][nt][2] + b0, v11 = acc[mt][nt][3] + b1;
                int h = c >> 6, d = c & 63;
                int b_ = r >> 10, mi = r & 1023;
                size_t bhO = (size_t)(b_ * 8 + h) * 65536;
                *(uint32_t*)(g_k + bhO + (size_t)mi * 64 + d) = pack2(v00, v01);
                *(uint32_t*)(g_k + bhO + (size_t)(mi + 8) * 64 + d) = pack2(v10, v11);
            }
        }
    } else {
        // V half: stage transposed tile in smem, then coalesced 16B row writes
        __syncthreads();                       // safe to reuse smem
        __half* vs = (__half*)smem;            // [128 cc][136 m] halves
        #pragma unroll
        for (int mt = 0; mt < 2; mt++) {
            #pragma unroll
            for (int nt = 0; nt < 8; nt++) {
                int rl = wm * 32 + mt * 16 + l2;           // local m 0..127
                int cl = wn * 64 + nt * 8 + l4 * 2;        // local cc 0..127
                int cg = n0 + cl;
                float b0 = bias[cg], b1 = bias[cg + 1];
                vs[cl * 136 + rl]           = __float2half_rn(acc[mt][nt][0] + b0);
                vs[(cl + 1) * 136 + rl]     = __float2half_rn(acc[mt][nt][1] + b1);
                vs[cl * 136 + rl + 8]       = __float2half_rn(acc[mt][nt][2] + b0);
                vs[(cl + 1) * 136 + rl + 8] = __float2half_rn(acc[mt][nt][3] + b1);
            }
        }
        __syncthreads();
        int row = tid >> 1, seg = tid & 1;     // row = cc local 0..127
        int cc = (n0 - 512) + row;
        int h = cc >> 6, d = cc & 63;
        int b_ = m0 >> 10, mi0 = m0 & 1023;
        __half* dst = g_v + (size_t)(b_ * 8 + h) * 65536 + (size_t)d * 1024
                      + mi0 + seg * 64;
        const __half* srcp = vs + row * 136 + seg * 64;
        #pragma unroll
        for (int i = 0; i < 8; i++)
            *(uint4*)(dst + i * 8) = *(const uint4*)(srcp + i * 8);
    }
}

// ---------------------------------------------------------------------------
// LayerNorm: sums 2 split-K partials, writes g_xrh (half). eps=1e-3.
// ---------------------------------------------------------------------------
__global__ void __launch_bounds__(128) ln_kernel(
    const float* __restrict__ gamma, const float* __restrict__ beta)
{
    int row = blockIdx.x;
    int t = threadIdx.x;
    size_t off = (size_t)row * 512 + t * 4;

    float4 v  = *(const float4*)(g_xr + off);
    float4 v2 = *(const float4*)(g_xr2 + off);
    v.x += v2.x; v.y += v2.y; v.z += v2.z; v.w += v2.w;

    float s  = v.x + v.y + v.z + v.w;
    float s2 = v.x * v.x + v.y * v.y + v.z * v.z + v.w * v.w;

    #pragma unroll
    for (int o = 16; o > 0; o >>= 1) {
        s  += __shfl_xor_sync(0xffffffffu, s, o);
        s2 += __shfl_xor_sync(0xffffffffu, s2, o);
    }
    __shared__ float red[2][4];
    int w = t >> 5;
    if ((t & 31) == 0) { red[0][w] = s; red[1][w] = s2; }
    __syncthreads();
    s  = red[0][0] + red[0][1] + red[0][2] + red[0][3];
    s2 = red[1][0] + red[1][1] + red[1][2] + red[1][3];

    float mu  = s * (1.0f / 512.0f);
    float var = s2 * (1.0f / 512.0f) - mu * mu;
    float inv = rsqrtf(var + 1e-3f);

    float4 g  = *(const float4*)(gamma + t * 4);
    float4 be = *(const float4*)(beta + t * 4);
    uint2 o;
    o.x = pack2((v.x - mu) * inv * g.x + be.x, (v.y - mu) * inv * g.y + be.y);
    o.y = pack2((v.z - mu) * inv * g.z + be.z, (v.w - mu) * inv * g.w + be.w);
    *(uint2*)(g_xrh + off) = o;
}

// ---------------------------------------------------------------------------
// Flash attention fp16: 128 threads / 4 warps, each warp owns 32 q rows;
// K/V fragments reused across both 16-row groups; softmax denominator via
// mma against a constant ones fragment; log2-domain ex2 softmax.
// 3-stage cp.async ring. smem u32: K[3][64][36] | V[3][64][36] = 55296 B.
// ---------------------------------------------------------------------------
__global__ void __launch_bounds__(128) attn_h()
{
    extern __shared__ uint32_t sm[];
    const int VOFF = 3 * 64 * 36;

    const int tid = threadIdx.x, lane = tid & 31, warp = tid >> 5;
    const int l2 = lane >> 2, l4 = lane & 3;
    const int bh = blockIdx.y, b = bh >> 3, h = bh & 7;
    const int q0 = blockIdx.x * 128;

    const __half* Kg = g_k + (size_t)bh * 65536;
    const __half* Vg = g_v + (size_t)bh * 65536;  // [d][m]

    const uint32_t sbase = (uint32_t)__cvta_generic_to_shared(sm);

    auto loadKV = [&](int s, int kv0) {
        #pragma unroll
        for (int u = 0; u < 4; u++) {
            int e = u * 128 + tid;
            int r = e >> 3, cw = e & 7;
            cp16(sbase + (uint32_t)(s * 2304 + r * 36 + cw * 4) * 4,
                 Kg + (size_t)(kv0 + r) * 64 + cw * 8);
            cp16(sbase + (uint32_t)(VOFF + s * 2304 + r * 36 + cw * 4) * 4,
                 Vg + (size_t)r * 1024 + kv0 + cw * 8);
        }
    };

    loadKV(0, 0);
    cp_commit();
    loadKV(1, 64);
    cp_commit();

    uint32_t qf[2][4][4];
    {
        const uint4* Qf = (const uint4*)g_q;
        #pragma unroll
        for (int g = 0; g < 2; g++) {
            size_t base = ((size_t)(bh * 256 + blockIdx.x * 8 + warp * 2 + g) * 4) * 32;
            #pragma unroll
            for (int j = 0; j < 4; j++) {
                uint4 v = Qf[base + j * 32 + lane];
                qf[g][j][0] = v.x; qf[g][j][1] = v.y;
                qf[g][j][2] = v.z; qf[g][j][3] = v.w;
            }
        }
    }

    float oacc[2][8][4] = {};
    float lsum[2][4] = {};
    const uint32_t onesf[2] = {0x3C003C00u, 0x3C003C00u};

    for (int kc = 0; kc < 16; kc++) {
        if (kc < 15) { cp_wait<1>(); } else { cp_wait<0>(); }
        __syncthreads();
        if (kc + 2 < 16) {
            loadKV((kc + 2) % 3, (kc + 2) * 64);
            cp_commit();
        }
        const int stage = kc % 3;

        float sacc[2][8][4] = {};
        const uint32_t* Kb = sm + stage * 2304;
        #pragma unroll
        for (int j = 0; j < 4; j++) {
            uint32_t bfr[8][2];
            #pragma unroll
            for (int nt = 0; nt < 8; nt++) {
                int kvi = nt * 8 + l2;
                bfr[nt][0] = Kb[kvi * 36 + j * 8 + l4];
                bfr[nt][1] = Kb[kvi * 36 + j * 8 + l4 + 4];
            }
            #pragma unroll
            for (int g = 0; g < 2; g++)
                #pragma unroll
                for (int nt = 0; nt < 8; nt++)
                    mma16(sacc[g][nt], qf[g][j], bfr[nt]);
        }

        const uint32_t* Vb = sm + VOFF + stage * 2304;
        #pragma unroll
        for (int j = 0; j < 4; j++) {
            uint32_t vfr[8][2];
            #pragma unroll
            for (int nt = 0; nt < 8; nt++) {
                int d = nt * 8 + l2;
                vfr[nt][0] = Vb[d * 36 + j * 8 + l4];
                vfr[nt][1] = Vb[d * 36 + j * 8 + l4 + 4];
            }
            #pragma unroll
            for (int g = 0; g < 2; g++) {
                uint32_t a[4];
                a[0] = h2ex2(pack2(sacc[g][2 * j][0],     sacc[g][2 * j][1]));
                a[1] = h2ex2(pack2(sacc[g][2 * j][2],     sacc[g][2 * j][3]));
                a[2] = h2ex2(pack2(sacc[g][2 * j + 1][0], sacc[g][2 * j + 1][1]));
                a[3] = h2ex2(pack2(sacc[g][2 * j + 1][2], sacc[g][2 * j + 1][3]));
                #pragma unroll
                for (int nt = 0; nt < 8; nt++)
                    mma16(oacc[g][nt], a, vfr[nt]);
                mma16(lsum[g], a, onesf);
            }
        }
    }

    #pragma unroll
    for (int g = 0; g < 2; g++) {
        float i0 = 1.0f / lsum[g][0];
        float i1 = 1.0f / lsum[g][2];
        int n = q0 + warp * 32 + g * 16 + l2;
        #pragma unroll
        for (int nt = 0; nt < 8; nt++) {
            int d = nt * 8 + l4 * 2;
            *(uint32_t*)(g_att + ((size_t)(b * 4096 + n) * 512 + h * 64 + d)) =
                pack2(oacc[g][nt][0] * i0, oacc[g][nt][1] * i0);
            *(uint32_t*)(g_att + ((size_t)(b * 4096 + n + 8) * 512 + h * 64 + d)) =
                pack2(oacc[g][nt][2] * i1, oacc[g][nt][3] * i1);
        }
    }
}

// ---------------------------------------------------------------------------
// Launcher
// ---------------------------------------------------------------------------
extern "C" void kernel_launch(void* const* d_in, const int* in_sizes, int n_in,
                              void* d_out, int out_size)
{
    const float *x = 0, *Wq = 0, *bq = 0, *Wkv = 0, *bkv = 0, *Wp = 0, *bp = 0;
    const float *srk = 0, *srb = 0, *gma = 0, *bta = 0;
    const float* s512[5] = {0, 0, 0, 0, 0};
    const float* s256k[2] = {0, 0};
    int n512 = 0, nbig = 0;

    for (int i = 0; i < n_in; i++) {
        int sz = in_sizes[i];
        const float* p = (const float*)d_in[i];
        if (sz == 8388608 && !x) x = p;
        else if (sz == 262144 && nbig < 2) s256k[nbig++] = p;
        else if (sz == 524288) Wkv = p;
        else if (sz == 1048576) srk = p;
        else if (sz == 1024) bkv = p;
        else if (sz == 512 && n512 < 5) s512[n512++] = p;
    }
    Wq = s256k[0]; Wp = s256k[1];
    bq = s512[0]; bp = s512[1]; srb = s512[2]; gma = s512[3]; bta = s512[4];
    float* out = (float*)d_out;

    const int wide_smem = (3 * 128 * 20 + 3 * 256 * 20) * 4;  // 92160
    const int nar_smem  = (3 * 128 * 20 + 3 * 128 * 20) * 4;  // 61440
    const int attn_smem = 6 * 64 * 36 * 4;                    // 55296
    cudaFuncSetAttribute(gemm_wide<0>, cudaFuncAttributeMaxDynamicSharedMemorySize, wide_smem);
    cudaFuncSetAttribute(gemm_wide<3>, cudaFuncAttributeMaxDynamicSharedMemorySize, wide_smem);
    cudaFuncSetAttribute(gemm_h<1>, cudaFuncAttributeMaxDynamicSharedMemorySize, nar_smem);
    cudaFuncSetAttribute(gemm_h<2>, cudaFuncAttributeMaxDynamicSharedMemorySize, nar_smem);
    cudaFuncSetAttribute(attn_h,  cudaFuncAttributeMaxDynamicSharedMemorySize, attn_smem);

    // merged pre-pass (x convert + weight transpose)
    prepass<<<10240, 256>>>((const float4*)x, Wq, Wkv, Wp, srk);
    // Q projection -> fragment-order g_q (log2-domain scale)
    gemm_wide<0><<<dim3(2, 128), 256, wide_smem>>>(bq, nullptr, 512);
    // SR conv as patch GEMM, split-K=2
    gemm_h<1><<<dim3(4, 32, 2), 256, nar_smem>>>(srb, 2048);
    // LayerNorm (sums 2 partials) -> g_xrh
    ln_kernel<<<4096, 128>>>(gma, bta);
    // KV projection -> g_k, g_v (V via smem transpose, coalesced writes)
    gemm_h<2><<<dim3(8, 32), 256, nar_smem>>>(bkv, 512);
    // attention (128 threads, 4 warps x 32 rows)
    attn_h<<<dim3(32, 32), 128, attn_smem>>>();
    // output projection -> d_out fp32
    gemm_wide<3><<<dim3(2, 128), 256, wide_smem>>>(bp, out, 512);
    (void)out_size;
}

// round 16
// speedup vs baseline: 1.0075x; 1.0075x over previous
#include <cuda_runtime.h>
#include <cuda_fp16.h>
#include <math.h>
#include <stdint.h>

// ---------------------------------------------------------------------------
// EfficientSelfAttention (PVT SRA): B=4, N=4096 (64x64), C=512, heads=8,
// head_dim=64, SR=2 -> N_kv=1024.  fp16 m16n8k16 mma.sync (fp32 accum).
// Round 16: R15 + attention occupancy 3 blocks/SM (launch_bounds(128,3),
// per-row-group restructure to halve live S registers).
// ---------------------------------------------------------------------------

__device__ __half  g_xt[8388608];   // x as half [16384][512]
__device__ float   g_xr[2097152];   // conv partial z=0 (fp32, +bias)
__device__ float   g_xr2[2097152];  // conv partial z=1
__device__ __half  g_xrh[2097152];  // LN output half
__device__ __half  g_k[2097152];    // [bh][m][d]
__device__ __half  g_v[2097152];    // TRANSPOSED: [bh][d][m]
__device__ __half  g_att[8388608];  // [b,n, h*64+d]
__device__ uint32_t g_q[4194304];   // Q in fp16 A-fragment order (log2-scaled)
__device__ __half  g_wq[262144];    // W^T [N][K]
__device__ __half  g_wkv[524288];
__device__ __half  g_wp[262144];
__device__ __half  g_wsr[1048576];

#define QSCALE 0.18033688011112042f   // 0.125 * log2(e)

__device__ __forceinline__ uint32_t pack2(float a, float b) {
    __half2 h = __floats2half2_rn(a, b);
    return *(uint32_t*)&h;
}
__device__ __forceinline__ uint32_t h2ex2(uint32_t x) {
    uint32_t r;
    asm("ex2.approx.f16x2 %0, %1;" : "=r"(r) : "r"(x));
    return r;
}

__device__ __forceinline__ void mma16(float* c, const uint32_t* a, const uint32_t* b) {
    asm("mma.sync.aligned.m16n8k16.row.col.f32.f16.f16.f32 "
        "{%0,%1,%2,%3}, {%4,%5,%6,%7}, {%8,%9}, {%0,%1,%2,%3};"
        : "+f"(c[0]), "+f"(c[1]), "+f"(c[2]), "+f"(c[3])
        : "r"(a[0]), "r"(a[1]), "r"(a[2]), "r"(a[3]), "r"(b[0]), "r"(b[1]));
}

__device__ __forceinline__ void cp16(uint32_t dst, const void* src) {
    asm volatile("cp.async.cg.shared.global [%0], [%1], 16;" :: "r"(dst), "l"(src));
}
__device__ __forceinline__ void cp_commit() {
    asm volatile("cp.async.commit_group;");
}
template <int N>
__device__ __forceinline__ void cp_wait() {
    asm volatile("cp.async.wait_group %0;" :: "n"(N));
}

// ---------------------------------------------------------------------------
// Merged pre-pass: blocks [0,8192) convert x -> half; [8192,10240) transpose
// weights fp32 [K][N] -> half [N][K].
// ---------------------------------------------------------------------------
__global__ void __launch_bounds__(256) prepass(
    const float4* __restrict__ x,
    const float* __restrict__ wq, const float* __restrict__ wkv,
    const float* __restrict__ wp, const float* __restrict__ wsr)
{
    __shared__ float tile[32][33];
    if (blockIdx.x < 8192) {
        int i = blockIdx.x * 256 + threadIdx.x;
        float4 v = x[i];
        uint2 o;
        o.x = pack2(v.x, v.y);
        o.y = pack2(v.z, v.w);
        *(uint2*)(g_xt + (size_t)i * 4) = o;
        return;
    }
    int t = blockIdx.x - 8192;
    const float* src; __half* dst; int K, N, tk, tn;
    if (t < 256)       { src = wq;  dst = g_wq;  K = 512;  N = 512;  tk = t >> 4; tn = t & 15; }
    else if (t < 768)  { t -= 256;  src = wkv; dst = g_wkv; K = 512;  N = 1024; tk = t >> 5; tn = t & 31; }
    else if (t < 1024) { t -= 768;  src = wp;  dst = g_wp;  K = 512;  N = 512;  tk = t >> 4; tn = t & 15; }
    else               { t -= 1024; src = wsr; dst = g_wsr; K = 2048; N = 512;  tk = t >> 4; tn = t & 15; }

    int tx = threadIdx.x & 31, ty = threadIdx.x >> 5;
    int k0 = tk * 32, n0 = tn * 32;
    #pragma unroll
    for (int i = 0; i < 4; i++)
        tile[tx][ty + 8 * i] = src[(size_t)(k0 + ty + 8 * i) * N + n0 + tx];
    __syncthreads();
    #pragma unroll
    for (int i = 0; i < 4; i++) {
        int row = ty + 8 * i;
        dst[(size_t)(n0 + row) * K + k0 + tx] = __float2half_rn(tile[row][tx]);
    }
}

// ---------------------------------------------------------------------------
// WIDE fp16 GEMM: block 128x256, BK=32, 3-stage cp.async ring, 8 warps (2x4),
// warp tile 64x64.
// MODE 0: A=g_xt,  B=g_wq^T -> g_q fragment-order (*QSCALE, +bias, half)
// MODE 3: A=g_att, B=g_wp^T -> Cout fp32 (+bias)
// ---------------------------------------------------------------------------
template <int MODE>
__global__ void __launch_bounds__(256) gemm_wide(
    const float* __restrict__ bias, float* __restrict__ Cout, int K)
{
    extern __shared__ uint32_t smem[];
    const int OB = 3 * 128 * 20;  // 7680

    const int tid = threadIdx.x, lane = tid & 31, warp = tid >> 5;
    const int wm = warp >> 2, wn = warp & 3;
    const int l2 = lane >> 2, l4 = lane & 3;
    const int m0 = blockIdx.y * 128, n0 = blockIdx.x * 256;

    const __half* Ap = (MODE == 3) ? g_att : g_xt;
    const __half* Bp = (MODE == 3) ? g_wp : g_wq;

    const uint32_t sbase = (uint32_t)__cvta_generic_to_shared(smem);

    float acc[4][8][4] = {};

    auto load_tiles = [&](int s, int k0) {
        #pragma unroll
        for (int u = 0; u < 2; u++) {
            int e = u * 256 + tid;
            int row = e >> 2, cw = e & 3;
            cp16(sbase + (uint32_t)(s * 2560 + row * 20 + cw * 4) * 4,
                 Ap + (size_t)(m0 + row) * K + k0 + cw * 8);
        }
        #pragma unroll
        for (int u = 0; u < 4; u++) {
            int e = u * 256 + tid;
            int row = e >> 2, cw = e & 3;
            cp16(sbase + (uint32_t)(OB + s * 5120 + row * 20 + cw * 4) * 4,
                 Bp + (size_t)(n0 + row) * K + k0 + cw * 8);
        }
    };

    const int KT = K >> 5;
    load_tiles(0, 0);
    cp_commit();
    load_tiles(1, 32);
    cp_commit();

    for (int kt = 0; kt < KT; kt++) {
        if (kt < KT - 1) { cp_wait<1>(); } else { cp_wait<0>(); }
        __syncthreads();
        if (kt + 2 < KT) {
            load_tiles((kt + 2) % 3, (kt + 2) * 32);
            cp_commit();
        }
        const int stage = kt % 3;

        const uint32_t* Ab = smem + stage * 2560;
        const uint32_t* Bb = smem + OB + stage * 5120;
        #pragma unroll
        for (int j = 0; j < 2; j++) {
            uint32_t a[4][4], bf[8][2];
            #pragma unroll
            for (int mt = 0; mt < 4; mt++) {
                int r = wm * 64 + mt * 16 + l2;
                a[mt][0] = Ab[r * 20 + j * 8 + l4];
                a[mt][1] = Ab[(r + 8) * 20 + j * 8 + l4];
                a[mt][2] = Ab[r * 20 + j * 8 + l4 + 4];
                a[mt][3] = Ab[(r + 8) * 20 + j * 8 + l4 + 4];
            }
            #pragma unroll
            for (int nt = 0; nt < 8; nt++) {
                int col = wn * 64 + nt * 8 + l2;
                bf[nt][0] = Bb[col * 20 + j * 8 + l4];
                bf[nt][1] = Bb[col * 20 + j * 8 + l4 + 4];
            }
            #pragma unroll
            for (int mt = 0; mt < 4; mt++)
                #pragma unroll
                for (int nt = 0; nt < 8; nt++)
                    mma16(acc[mt][nt], a[mt], bf[nt]);
        }
        __syncthreads();
    }

    #pragma unroll
    for (int mt = 0; mt < 4; mt++) {
        #pragma unroll
        for (int nt = 0; nt < 8; nt++) {
            int r = m0 + wm * 64 + mt * 16 + l2;
            int c = n0 + wn * 64 + nt * 8 + l4 * 2;
            float b0 = bias[c], b1 = bias[c + 1];
            float v00 = acc[mt][nt][0] + b0, v01 = acc[mt][nt][1] + b1;
            float v10 = acc[mt][nt][2] + b0, v11 = acc[mt][nt][3] + b1;
            if (MODE == 0) {
                int b_ = r >> 12, nq = r & 4095;
                int h = c >> 6, d = c & 63;
                int bh = b_ * 8 + h, ntile = nq >> 4;
                int j = d >> 4, wsel = (d >> 3) & 1;
                size_t base = (((size_t)(bh * 256 + ntile) * 4 + j) * 32 + lane) * 4 + wsel * 2;
                g_q[base]     = pack2(v00 * QSCALE, v01 * QSCALE);
                g_q[base + 1] = pack2(v10 * QSCALE, v11 * QSCALE);
            } else {
                *(float2*)(Cout + (size_t)r * 512 + c) = make_float2(v00, v01);
                *(float2*)(Cout + (size_t)(r + 8) * 512 + c) = make_float2(v10, v11);
            }
        }
    }
}

// ---------------------------------------------------------------------------
// Narrow fp16 GEMM: block 128x128, BK=32, 3-stage ring, warp tile 32x64.
// MODE 1: A=g_xt (conv patch gather), B=g_wsr^T -> split-K z=0/1 partials
// MODE 2: A=g_xrh, B=g_wkv^T -> g_k (+bias) / g_v (smem-transposed, +bias)
// ---------------------------------------------------------------------------
template <int MODE>
__global__ void __launch_bounds__(256) gemm_h(
    const float* __restrict__ bias, int Kfull)
{
    extern __shared__ uint32_t smem[];
    const int OB = 3 * 128 * 20;

    const int tid = threadIdx.x, lane = tid & 31, warp = tid >> 5;
    const int wm = warp >> 1, wn = warp & 1;
    const int l2 = lane >> 2, l4 = lane & 3;
    const int m0 = blockIdx.y * 128, n0 = blockIdx.x * 128;
    const int kz0 = (MODE == 1) ? (int)blockIdx.z * 1024 : 0;
    const int Kblk = (MODE == 1) ? 1024 : Kfull;

    const __half* Ap = (MODE == 2) ? g_xrh : g_xt;
    const __half* Bp = (MODE == 1) ? g_wsr : g_wkv;

    const uint32_t sbase = (uint32_t)__cvta_generic_to_shared(smem);

    float acc[2][8][4] = {};

    auto load_tiles = [&](int s, int kg) {
        #pragma unroll
        for (int u = 0; u < 2; u++) {
            int e = u * 256 + tid;
            int row = e >> 2, cw = e & 3;
            const __half* src;
            if (MODE == 1) {
                int m = m0 + row;
                int b = m >> 10, rem = m & 1023;
                int oh = rem >> 5, ow = rem & 31;
                int k = kg + cw * 8;
                int di = k >> 10, dj = (k >> 9) & 1, c = k & 511;
                int grow = (b << 12) + (((oh << 1) + di) << 6) + (ow << 1) + dj;
                src = Ap + (size_t)grow * 512 + c;
            } else {
                src = Ap + (size_t)(m0 + row) * Kfull + kg + cw * 8;
            }
            cp16(sbase + (uint32_t)(s * 2560 + row * 20 + cw * 4) * 4, src);
        }
        #pragma unroll
        for (int u = 0; u < 2; u++) {
            int e = u * 256 + tid;
            int row = e >> 2, cw = e & 3;
            cp16(sbase + (uint32_t)(OB + s * 2560 + row * 20 + cw * 4) * 4,
                 Bp + (size_t)(n0 + row) * Kfull + kg + cw * 8);
        }
    };

    const int KT = Kblk >> 5;
    load_tiles(0, kz0);
    cp_commit();
    load_tiles(1, kz0 + 32);
    cp_commit();

    for (int kt = 0; kt < KT; kt++) {
        if (kt < KT - 1) { cp_wait<1>(); } else { cp_wait<0>(); }
        __syncthreads();
        if (kt + 2 < KT) {
            load_tiles((kt + 2) % 3, kz0 + (kt + 2) * 32);
            cp_commit();
        }
        const int stage = kt % 3;

        const uint32_t* Ab = smem + stage * 2560;
        const uint32_t* Bb = smem + OB + stage * 2560;
        #pragma unroll
        for (int j = 0; j < 2; j++) {
            uint32_t a[2][4], bf[8][2];
            #pragma unroll
            for (int mt = 0; mt < 2; mt++) {
                int r = wm * 32 + mt * 16 + l2;
                a[mt][0] = Ab[r * 20 + j * 8 + l4];
                a[mt][1] = Ab[(r + 8) * 20 + j * 8 + l4];
                a[mt][2] = Ab[r * 20 + j * 8 + l4 + 4];
                a[mt][3] = Ab[(r + 8) * 20 + j * 8 + l4 + 4];
            }
            #pragma unroll
            for (int nt = 0; nt < 8; nt++) {
                int col = wn * 64 + nt * 8 + l2;
                bf[nt][0] = Bb[col * 20 + j * 8 + l4];
                bf[nt][1] = Bb[col * 20 + j * 8 + l4 + 4];
            }
            #pragma unroll
            for (int mt = 0; mt < 2; mt++)
                #pragma unroll
                for (int nt = 0; nt < 8; nt++)
                    mma16(acc[mt][nt], a[mt], bf[nt]);
        }
        __syncthreads();
    }

    if (MODE == 1) {
        #pragma unroll
        for (int mt = 0; mt < 2; mt++) {
            #pragma unroll
            for (int nt = 0; nt < 8; nt++) {
                int r = m0 + wm * 32 + mt * 16 + l2;
                int c = n0 + wn * 64 + nt * 8 + l4 * 2;
                float b0 = 0.0f, b1 = 0.0f;
                if (blockIdx.z == 0) { b0 = bias[c]; b1 = bias[c + 1]; }
                float* dst = (blockIdx.z == 0) ? g_xr : g_xr2;
                *(float2*)(dst + (size_t)r * 512 + c) =
                    make_float2(acc[mt][nt][0] + b0, acc[mt][nt][1] + b1);
                *(float2*)(dst + (size_t)(r + 8) * 512 + c) =
                    make_float2(acc[mt][nt][2] + b0, acc[mt][nt][3] + b1);
            }
        }
        return;
    }

    // MODE 2 epilogue
    if (n0 < 512) {
        #pragma unroll
        for (int mt = 0; mt < 2; mt++) {
            #pragma unroll
            for (int nt = 0; nt < 8; nt++) {
                int r = m0 + wm * 32 + mt * 16 + l2;
                int c = n0 + wn * 64 + nt * 8 + l4 * 2;
                float b0 = bias[c], b1 = bias[c + 1];
                float v00 = acc[mt][nt][0] + b0, v01 = acc[mt][nt][1] + b1;
                float v10 = acc[mt][nt][2] + b0, v11 = acc[mt][nt][3] + b1;
                int h = c >> 6, d = c & 63;
                int b_ = r >> 10, mi = r & 1023;
                size_t bhO = (size_t)(b_ * 8 + h) * 65536;
                *(uint32_t*)(g_k + bhO + (size_t)mi * 64 + d) = pack2(v00, v01);
                *(uint32_t*)(g_k + bhO + (size_t)(mi + 8) * 64 + d) = pack2(v10, v11);
            }
        }
    } else {
        // V half: stage transposed tile in smem, then coalesced 16B row writes
        __syncthreads();
        __half* vs = (__half*)smem;            // [128 cc][136 m] halves
        #pragma unroll
        for (int mt = 0; mt < 2; mt++) {
            #pragma unroll
            for (int nt = 0; nt < 8; nt++) {
                int rl = wm * 32 + mt * 16 + l2;
                int cl = wn * 64 + nt * 8 + l4 * 2;
                int cg = n0 + cl;
                float b0 = bias[cg], b1 = bias[cg + 1];
                vs[cl * 136 + rl]           = __float2half_rn(acc[mt][nt][0] + b0);
                vs[(cl + 1) * 136 + rl]     = __float2half_rn(acc[mt][nt][1] + b1);
                vs[cl * 136 + rl + 8]       = __float2half_rn(acc[mt][nt][2] + b0);
                vs[(cl + 1) * 136 + rl + 8] = __float2half_rn(acc[mt][nt][3] + b1);
            }
        }
        __syncthreads();
        int row = tid >> 1, seg = tid & 1;
        int cc = (n0 - 512) + row;
        int h = cc >> 6, d = cc & 63;
        int b_ = m0 >> 10, mi0 = m0 & 1023;
        __half* dst = g_v + (size_t)(b_ * 8 + h) * 65536 + (size_t)d * 1024
                      + mi0 + seg * 64;
        const __half* srcp = vs + row * 136 + seg * 64;
        #pragma unroll
        for (int i = 0; i < 8; i++)
            *(uint4*)(dst + i * 8) = *(const uint4*)(srcp + i * 8);
    }
}

// ---------------------------------------------------------------------------
// LayerNorm: sums 2 split-K partials, writes g_xrh (half). eps=1e-3.
// ---------------------------------------------------------------------------
__global__ void __launch_bounds__(128) ln_kernel(
    const float* __restrict__ gamma, const float* __restrict__ beta)
{
    int row = blockIdx.x;
    int t = threadIdx.x;
    size_t off = (size_t)row * 512 + t * 4;

    float4 v  = *(const float4*)(g_xr + off);
    float4 v2 = *(const float4*)(g_xr2 + off);
    v.x += v2.x; v.y += v2.y; v.z += v2.z; v.w += v2.w;

    float s  = v.x + v.y + v.z + v.w;
    float s2 = v.x * v.x + v.y * v.y + v.z * v.z + v.w * v.w;

    #pragma unroll
    for (int o = 16; o > 0; o >>= 1) {
        s  += __shfl_xor_sync(0xffffffffu, s, o);
        s2 += __shfl_xor_sync(0xffffffffu, s2, o);
    }
    __shared__ float red[2][4];
    int w = t >> 5;
    if ((t & 31) == 0) { red[0][w] = s; red[1][w] = s2; }
    __syncthreads();
    s  = red[0][0] + red[0][1] + red[0][2] + red[0][3];
    s2 = red[1][0] + red[1][1] + red[1][2] + red[1][3];

    float mu  = s * (1.0f / 512.0f);
    float var = s2 * (1.0f / 512.0f) - mu * mu;
    float inv = rsqrtf(var + 1e-3f);

    float4 g  = *(const float4*)(gamma + t * 4);
    float4 be = *(const float4*)(beta + t * 4);
    uint2 o;
    o.x = pack2((v.x - mu) * inv * g.x + be.x, (v.y - mu) * inv * g.y + be.y);
    o.y = pack2((v.z - mu) * inv * g.z + be.z, (v.w - mu) * inv * g.w + be.w);
    *(uint2*)(g_xrh + off) = o;
}

// ---------------------------------------------------------------------------
// Flash attention fp16: 128 threads / 4 warps, each warp owns 32 q rows as
// two 16-row groups processed SEQUENTIALLY (halves live S registers so
// launch_bounds(128,3) fits 3 blocks/SM). Softmax denominator via mma
// against a constant ones fragment; log2-domain ex2 softmax.
// 3-stage cp.async ring. smem u32: K[3][64][36] | V[3][64][36] = 55296 B.
// ---------------------------------------------------------------------------
__global__ void __launch_bounds__(128, 3) attn_h()
{
    extern __shared__ uint32_t sm[];
    const int VOFF = 3 * 64 * 36;

    const int tid = threadIdx.x, lane = tid & 31, warp = tid >> 5;
    const int l2 = lane >> 2, l4 = lane & 3;
    const int bh = blockIdx.y, b = bh >> 3, h = bh & 7;
    const int q0 = blockIdx.x * 128;

    const __half* Kg = g_k + (size_t)bh * 65536;
    const __half* Vg = g_v + (size_t)bh * 65536;  // [d][m]

    const uint32_t sbase = (uint32_t)__cvta_generic_to_shared(sm);

    auto loadKV = [&](int s, int kv0) {
        #pragma unroll
        for (int u = 0; u < 4; u++) {
            int e = u * 128 + tid;
            int r = e >> 3, cw = e & 7;
            cp16(sbase + (uint32_t)(s * 2304 + r * 36 + cw * 4) * 4,
                 Kg + (size_t)(kv0 + r) * 64 + cw * 8);
            cp16(sbase + (uint32_t)(VOFF + s * 2304 + r * 36 + cw * 4) * 4,
                 Vg + (size_t)r * 1024 + kv0 + cw * 8);
        }
    };

    loadKV(0, 0);
    cp_commit();
    loadKV(1, 64);
    cp_commit();

    uint32_t qf[2][4][4];
    {
        const uint4* Qf = (const uint4*)g_q;
        #pragma unroll
        for (int g = 0; g < 2; g++) {
            size_t base = ((size_t)(bh * 256 + blockIdx.x * 8 + warp * 2 + g) * 4) * 32;
            #pragma unroll
            for (int j = 0; j < 4; j++) {
                uint4 v = Qf[base + j * 32 + lane];
                qf[g][j][0] = v.x; qf[g][j][1] = v.y;
                qf[g][j][2] = v.z; qf[g][j][3] = v.w;
            }
        }
    }

    float oacc[2][8][4] = {};
    float lsum[2][4] = {};
    const uint32_t onesf[2] = {0x3C003C00u, 0x3C003C00u};

    for (int kc = 0; kc < 16; kc++) {
        if (kc < 15) { cp_wait<1>(); } else { cp_wait<0>(); }
        __syncthreads();
        if (kc + 2 < 16) {
            loadKV((kc + 2) % 3, (kc + 2) * 64);
            cp_commit();
        }
        const int stage = kc % 3;
        const uint32_t* Kb = sm + stage * 2304;
        const uint32_t* Vb = sm + VOFF + stage * 2304;

        // process the two 16-row groups sequentially: sacc live range halved
        #pragma unroll
        for (int g = 0; g < 2; g++) {
            float sacc[8][4] = {};
            #pragma unroll
            for (int j = 0; j < 4; j++) {
                #pragma unroll
                for (int nt = 0; nt < 8; nt++) {
                    uint32_t bfr[2];
                    int kvi = nt * 8 + l2;
                    bfr[0] = Kb[kvi * 36 + j * 8 + l4];
                    bfr[1] = Kb[kvi * 36 + j * 8 + l4 + 4];
                    mma16(sacc[nt], qf[g][j], bfr);
                }
            }
            #pragma unroll
            for (int j = 0; j < 4; j++) {
                uint32_t a[4];
                a[0] = h2ex2(pack2(sacc[2 * j][0],     sacc[2 * j][1]));
                a[1] = h2ex2(pack2(sacc[2 * j][2],     sacc[2 * j][3]));
                a[2] = h2ex2(pack2(sacc[2 * j + 1][0], sacc[2 * j + 1][1]));
                a[3] = h2ex2(pack2(sacc[2 * j + 1][2], sacc[2 * j + 1][3]));
                #pragma unroll
                for (int nt = 0; nt < 8; nt++) {
                    uint32_t vfr[2];
                    int d = nt * 8 + l2;
                    vfr[0] = Vb[d * 36 + j * 8 + l4];
                    vfr[1] = Vb[d * 36 + j * 8 + l4 + 4];
                    mma16(oacc[g][nt], a, vfr);
                }
                mma16(lsum[g], a, onesf);
            }
        }
    }

    #pragma unroll
    for (int g = 0; g < 2; g++) {
        float i0 = 1.0f / lsum[g][0];
        float i1 = 1.0f / lsum[g][2];
        int n = q0 + warp * 32 + g * 16 + l2;
        #pragma unroll
        for (int nt = 0; nt < 8; nt++) {
            int d = nt * 8 + l4 * 2;
            *(uint32_t*)(g_att + ((size_t)(b * 4096 + n) * 512 + h * 64 + d)) =
                pack2(oacc[g][nt][0] * i0, oacc[g][nt][1] * i0);
            *(uint32_t*)(g_att + ((size_t)(b * 4096 + n + 8) * 512 + h * 64 + d)) =
                pack2(oacc[g][nt][2] * i1, oacc[g][nt][3] * i1);
        }
    }
}

// ---------------------------------------------------------------------------
// Launcher
// ---------------------------------------------------------------------------
extern "C" void kernel_launch(void* const* d_in, const int* in_sizes, int n_in,
                              void* d_out, int out_size)
{
    const float *x = 0, *Wq = 0, *bq = 0, *Wkv = 0, *bkv = 0, *Wp = 0, *bp = 0;
    const float *srk = 0, *srb = 0, *gma = 0, *bta = 0;
    const float* s512[5] = {0, 0, 0, 0, 0};
    const float* s256k[2] = {0, 0};
    int n512 = 0, nbig = 0;

    for (int i = 0; i < n_in; i++) {
        int sz = in_sizes[i];
        const float* p = (const float*)d_in[i];
        if (sz == 8388608 && !x) x = p;
        else if (sz == 262144 && nbig < 2) s256k[nbig++] = p;
        else if (sz == 524288) Wkv = p;
        else if (sz == 1048576) srk = p;
        else if (sz == 1024) bkv = p;
        else if (sz == 512 && n512 < 5) s512[n512++] = p;
    }
    Wq = s256k[0]; Wp = s256k[1];
    bq = s512[0]; bp = s512[1]; srb = s512[2]; gma = s512[3]; bta = s512[4];
    float* out = (float*)d_out;

    const int wide_smem = (3 * 128 * 20 + 3 * 256 * 20) * 4;  // 92160
    const int nar_smem  = (3 * 128 * 20 + 3 * 128 * 20) * 4;  // 61440
    const int attn_smem = 6 * 64 * 36 * 4;                    // 55296
    cudaFuncSetAttribute(gemm_wide<0>, cudaFuncAttributeMaxDynamicSharedMemorySize, wide_smem);
    cudaFuncSetAttribute(gemm_wide<3>, cudaFuncAttributeMaxDynamicSharedMemorySize, wide_smem);
    cudaFuncSetAttribute(gemm_h<1>, cudaFuncAttributeMaxDynamicSharedMemorySize, nar_smem);
    cudaFuncSetAttribute(gemm_h<2>, cudaFuncAttributeMaxDynamicSharedMemorySize, nar_smem);
    cudaFuncSetAttribute(attn_h,  cudaFuncAttributeMaxDynamicSharedMemorySize, attn_smem);

    // merged pre-pass (x convert + weight transpose)
    prepass<<<10240, 256>>>((const float4*)x, Wq, Wkv, Wp, srk);
    // Q projection -> fragment-order g_q (log2-domain scale)
    gemm_wide<0><<<dim3(2, 128), 256, wide_smem>>>(bq, nullptr, 512);
    // SR conv as patch GEMM, split-K=2
    gemm_h<1><<<dim3(4, 32, 2), 256, nar_smem>>>(srb, 2048);
    // LayerNorm (sums 2 partials) -> g_xrh
    ln_kernel<<<4096, 128>>>(gma, bta);
    // KV projection -> g_k, g_v (V via smem transpose, coalesced writes)
    gemm_h<2><<<dim3(8, 32), 256, nar_smem>>>(bkv, 512);
    // attention (128 threads, 4 warps x 32 rows, 3 blocks/SM)
    attn_h<<<dim3(32, 32), 128, attn_smem>>>();
    // output projection -> d_out fp32
    gemm_wide<3><<<dim3(2, 128), 256, wide_smem>>>(bp, out, 512);
    (void)out_size;
}